// round 16
// baseline (speedup 1.0000x reference)
#include <cuda_runtime.h>
#include <cuda_fp16.h>
#include <cstdint>

#define M_TOT 32768
#define N_TOT 1024
#define K_TOT 1024
#define BM 128
#define BN 128
#define BK 64
#define STAGES 3
#define TILE_BYTES 16384               // one 128x64 fp16 tile, swizzled
#define STAGE_BYTES (2 * TILE_BYTES)   // A tile + B tile
#define NKT (K_TOT / BK)               // 16
#define SLAB_BYTES ((size_t)NKT * TILE_BYTES)
#define PRE_BLOCKS 8192                // A-precompute blocks (2 half8/thread)
#define PERM_BLOCKS 512

// scratch, both stored TILED + SWIZZLED:
//   g_Ah:  [bm_blk=256][kt=16][128x64 tile, 16KB, xor-swizzled]   (64 MB)
//   g_Wph: [bn_blk=8  ][kt=16][128x64 tile, 16KB, xor-swizzled]   ( 2 MB)
__device__ __half g_Ah[(size_t)M_TOT * K_TOT];
__device__ __half g_Wph[N_TOT * K_TOT];

__device__ __forceinline__ uint32_t tile_off(int row, int cc) {
    return (uint32_t)row * 128u + (uint32_t)((cc ^ (row & 7)) << 4);
}

// ---------------------------------------------------------------------------
// Kernel 0 (fused prep):
//  blocks [0, PRE_BLOCKS): A = fp16(__cosf(x+theta)); 2 adjacent half8 chunks
//    per thread (64B contiguous read, 32B write) for 2x memory-level parallelism
//  blocks [PRE_BLOCKS, +PERM_BLOCKS): Wph[n, h*4+q] = fp16(W[n, q*256+h])
// ---------------------------------------------------------------------------
__global__ void prep_kernel(const float* __restrict__ X,
                            const float* __restrict__ theta,
                            const float* __restrict__ W) {
    if (blockIdx.x < PRE_BLOCKS) {
        const size_t tg = (size_t)blockIdx.x * 256 + threadIdx.x;  // 0..2M-1
        const int m = (int)(tg >> 6);          // row
        const int k8 = 2 * (int)(tg & 63);     // first half8 chunk (even)
        const float4* X4  = (const float4*)X;
        const float4* Th4 = (const float4*)theta;
        const float4 t0 = __ldg(Th4 + 2 * k8);
        const float4 t1 = __ldg(Th4 + 2 * k8 + 1);
        const float4 t2 = __ldg(Th4 + 2 * k8 + 2);
        const float4 t3 = __ldg(Th4 + 2 * k8 + 3);
        const float4 v0 = __ldg(X4 + (size_t)m * 256 + 2 * k8);
        const float4 v1 = __ldg(X4 + (size_t)m * 256 + 2 * k8 + 1);
        const float4 v2 = __ldg(X4 + (size_t)m * 256 + 2 * k8 + 2);
        const float4 v3 = __ldg(X4 + (size_t)m * 256 + 2 * k8 + 3);
        __half h[16];
        h[0]  = __float2half_rn(__cosf(v0.x + t0.x));
        h[1]  = __float2half_rn(__cosf(v0.y + t0.y));
        h[2]  = __float2half_rn(__cosf(v0.z + t0.z));
        h[3]  = __float2half_rn(__cosf(v0.w + t0.w));
        h[4]  = __float2half_rn(__cosf(v1.x + t1.x));
        h[5]  = __float2half_rn(__cosf(v1.y + t1.y));
        h[6]  = __float2half_rn(__cosf(v1.z + t1.z));
        h[7]  = __float2half_rn(__cosf(v1.w + t1.w));
        h[8]  = __float2half_rn(__cosf(v2.x + t2.x));
        h[9]  = __float2half_rn(__cosf(v2.y + t2.y));
        h[10] = __float2half_rn(__cosf(v2.z + t2.z));
        h[11] = __float2half_rn(__cosf(v2.w + t2.w));
        h[12] = __float2half_rn(__cosf(v3.x + t3.x));
        h[13] = __float2half_rn(__cosf(v3.y + t3.y));
        h[14] = __float2half_rn(__cosf(v3.z + t3.z));
        h[15] = __float2half_rn(__cosf(v3.w + t3.w));
        const int bm_blk = m >> 7;
        const int rowloc = m & 127;
        char* slab = (char*)g_Ah + (size_t)bm_blk * SLAB_BYTES
                   + (size_t)(k8 >> 3) * TILE_BYTES;   // both chunks same tile
        *(uint4*)(slab + tile_off(rowloc, k8 & 7))       = *(const uint4*)h;
        *(uint4*)(slab + tile_off(rowloc, (k8 + 1) & 7)) = *(const uint4*)(h + 8);
    } else {
        const int base = ((int)blockIdx.x - PRE_BLOCKS) * (256 * 8)
                       + (int)threadIdx.x * 8;
#pragma unroll
        for (int e = 0; e < 8; e++) {
            const int idx = base + e;          // 0 .. 1M-1
            const int n = idx >> 10;
            const int j = idx & 1023;
            const int q = j >> 8;
            const int hh = j & 255;
            const int k = (hh << 2) | q;
            const int bn_blk = n >> 7;
            const int rowloc = n & 127;
            const size_t dst = (size_t)bn_blk * SLAB_BYTES
                             + (size_t)(k >> 6) * TILE_BYTES
                             + tile_off(rowloc, (k >> 3) & 7)
                             + (size_t)((k & 7) * 2);
            *(__half*)((char*)g_Wph + dst) = __float2half_rn(__ldg(W + idx));
        }
    }
}

// ---------------------------------------------------------------------------
// helpers
// ---------------------------------------------------------------------------
__device__ __forceinline__ uint32_t smem_u32(const void* p) {
    uint32_t a;
    asm("{ .reg .u64 t; cvta.to.shared.u64 t, %1; cvt.u32.u64 %0, t; }"
        : "=r"(a) : "l"(p));
    return a;
}

#define MBAR_INIT(addr, cnt) \
    asm volatile("mbarrier.init.shared.b64 [%0], %1;" :: "r"(addr), "r"(cnt) : "memory")

#define MBAR_EXPECT_TX(addr, bytes) \
    asm volatile("mbarrier.arrive.expect_tx.shared.b64 _, [%0], %1;" \
                 :: "r"(addr), "r"(bytes) : "memory")

#define MBAR_ARRIVE(addr) \
    asm volatile("mbarrier.arrive.release.cta.shared.b64 _, [%0];" \
                 :: "r"(addr) : "memory")

#define MBAR_WAIT(addr, parity) do {                                              \
    asm volatile("{\n\t.reg .pred P1;\n\t"                                        \
        "LAB_W_%=:\n\t"                                                           \
        "mbarrier.try_wait.parity.acquire.cta.shared::cta.b64 P1, [%0], %1, 0x989680;\n\t" \
        "@P1 bra.uni LAB_D_%=;\n\t"                                               \
        "bra.uni LAB_W_%=;\n\t"                                                   \
        "LAB_D_%=:\n\t}"                                                          \
        :: "r"(addr), "r"(parity) : "memory");                                    \
} while (0)

#define FENCE_ASYNC() \
    asm volatile("fence.proxy.async.shared::cta;" ::: "memory")

#define BULK_CP(dst, src, bytes, mbar) \
    asm volatile("cp.async.bulk.shared::cluster.global.mbarrier::complete_tx::bytes " \
                 "[%0], [%1], %2, [%3];" \
                 :: "r"(dst), "l"(src), "r"(bytes), "r"(mbar) : "memory")

__device__ __forceinline__ void ldsm_x4(uint32_t* r, uint32_t addr) {
    asm volatile("ldmatrix.sync.aligned.m8n8.x4.shared.b16 {%0,%1,%2,%3}, [%4];"
                 : "=r"(r[0]), "=r"(r[1]), "=r"(r[2]), "=r"(r[3]) : "r"(addr));
}

__device__ __forceinline__ void mma_f16(float* c, const uint32_t* a,
                                        const uint32_t* b) {
    asm volatile(
        "mma.sync.aligned.m16n8k16.row.col.f32.f16.f16.f32 "
        "{%0,%1,%2,%3}, {%4,%5,%6,%7}, {%8,%9}, {%0,%1,%2,%3};\n"
        : "+f"(c[0]), "+f"(c[1]), "+f"(c[2]), "+f"(c[3])
        : "r"(a[0]), "r"(a[1]), "r"(a[2]), "r"(a[3]), "r"(b[0]), "r"(b[1]));
}

// ---------------------------------------------------------------------------
// Kernel 1: out = Ah @ Wph^T + bias   (R9 GEMM + ROTATING issuer)
//   block 128x128, BK=64, 4 warps (2M x 2N), warp tile 64x64, 2 CTA/SM,
//   3-stage cp.async.bulk + full/empty mbarriers + proxy fence.
//   Pipeline bookkeeping (empty-wait + fence + bulk issue) rotates across
//   warps: warp (kt & 3) issues at iteration kt -> no single SMSP lags.
//   Parities are pure functions of kt (verified == R9's sequential trace).
// ---------------------------------------------------------------------------
__global__ void __launch_bounds__(128, 2)
qmha_gemm_kernel(const float* __restrict__ bias, float* __restrict__ out) {
    extern __shared__ char dsm[];
    __shared__ __align__(8) uint64_t bar_s[2 * STAGES];   // full[3], empty[3]

    const uint32_t base = (smem_u32(dsm) + 1023u) & ~1023u;
    const uint32_t full_bar  = smem_u32(bar_s);
    const uint32_t empty_bar = full_bar + 8 * STAGES;

    const int tid  = threadIdx.x;
    const int warp = tid >> 5;
    const int lane = tid & 31;
    const int g    = lane >> 2;
    const int t    = lane & 3;
    const int wm   = (warp & 1) * 64;     // 2 warps along M
    const int wn   = (warp >> 1) * 64;    // 2 warps along N

    // block swizzle: N fastest -> co-resident blocks share A slab in L2
    const int bn_blk = blockIdx.x & 7;
    const int bm_blk = blockIdx.x >> 3;
    const int bn = bn_blk * BN;
    const int bm = bm_blk * BM;

    const char* aChunk = (const char*)g_Ah + (size_t)bm_blk * SLAB_BYTES;
    const char* bChunk = (const char*)g_Wph + (size_t)bn_blk * SLAB_BYTES;

    if (tid == 0) {
#pragma unroll
        for (int s = 0; s < STAGES; s++) {
            MBAR_INIT(full_bar + 8 * s, 1);
            MBAR_INIT(empty_bar + 8 * s, 4);    // one arrive per warp
        }
    }
    __syncthreads();

    auto ISSUE = [&](int s, int kt) {
        const uint32_t fb = full_bar + 8 * s;
        MBAR_EXPECT_TX(fb, STAGE_BYTES);
        BULK_CP(base + s * STAGE_BYTES, aChunk + (size_t)kt * TILE_BYTES,
                TILE_BYTES, fb);
        BULK_CP(base + s * STAGE_BYTES + TILE_BYTES,
                bChunk + (size_t)kt * TILE_BYTES, TILE_BYTES, fb);
    };

    // prologue (stages 0,1 known-empty: no wait needed)
    if (tid == 0) { ISSUE(0, 0); ISSUE(1, 1); }

    // ldmatrix per-lane address components
    const int rA  = lane & 15;
    const int aHi = lane >> 4;
    const uint32_t aRowB = (uint32_t)(wm + rA) * 128;
    const uint32_t aSw   = (uint32_t)(rA & 7);
    const int nLoc = (lane & 7) | ((lane >> 4) << 3);
    const int bHi  = (lane >> 3) & 1;
    const uint32_t bRowB = (uint32_t)(wn + nLoc) * 128;
    const uint32_t bSw   = (uint32_t)(nLoc & 7);

    float acc[4][8][4];
#pragma unroll
    for (int m = 0; m < 4; m++)
#pragma unroll
        for (int n = 0; n < 8; n++)
#pragma unroll
            for (int v = 0; v < 4; v++) acc[m][n][v] = 0.f;

    int stage = 0;
    for (int kt = 0; kt < NKT; kt++) {
        const uint32_t third = (uint32_t)(kt / 3);

        // rotating issuer: warp (kt&3), lane 0, refills stage (kt+2)%3
        if (warp == (kt & 3) && lane == 0 && kt + 2 < NKT) {
            const int s2 = stage + 2 >= STAGES ? stage + 2 - STAGES : stage + 2;
            const uint32_t pe = (third & 1u) ^ (s2 == 2 ? 1u : 0u);
            MBAR_WAIT(empty_bar + 8 * s2, pe);
            FENCE_ASYNC();              // order generic reads before TMA rewrite
            ISSUE(s2, kt + 2);
        }

        MBAR_WAIT(full_bar + 8 * stage, third & 1u);

        const uint32_t aS = base + stage * STAGE_BYTES + aRowB;
        const uint32_t bS = base + stage * STAGE_BYTES + TILE_BYTES + bRowB;
#pragma unroll
        for (int ks = 0; ks < 4; ks++) {               // 4 x k16 per BK=64
            const uint32_t ca = (uint32_t)((((2 * ks) | aHi) ^ aSw) << 4);
            const uint32_t cb = (uint32_t)((((2 * ks) | bHi) ^ bSw) << 4);
            uint32_t af[4][4], bf[4][4];
#pragma unroll
            for (int mt = 0; mt < 4; mt++)
                ldsm_x4(af[mt], aS + mt * 2048 + ca);
#pragma unroll
            for (int p = 0; p < 4; p++)
                ldsm_x4(bf[p], bS + p * 2048 + cb);
#pragma unroll
            for (int mt = 0; mt < 4; mt++)
#pragma unroll
                for (int nt = 0; nt < 8; nt++)
                    mma_f16(acc[mt][nt], af[mt], &bf[nt >> 1][(nt & 1) * 2]);
        }

        if (lane == 0) MBAR_ARRIVE(empty_bar + 8 * stage);

        stage = stage + 1 >= STAGES ? 0 : stage + 1;
    }

    // epilogue: + bias, fp32 out (64x64 per warp)
#pragma unroll
    for (int mt = 0; mt < 4; mt++) {
        const int m = bm + wm + mt * 16 + g;
#pragma unroll
        for (int nt = 0; nt < 8; nt++) {
            const int n = bn + wn + nt * 8 + 2 * t;
            const float b0 = __ldg(bias + n);
            const float b1 = __ldg(bias + n + 1);
            *(float2*)(out + (size_t)m * N_TOT + n) =
                make_float2(acc[mt][nt][0] + b0, acc[mt][nt][1] + b1);
            *(float2*)(out + (size_t)(m + 8) * N_TOT + n) =
                make_float2(acc[mt][nt][2] + b0, acc[mt][nt][3] + b1);
        }
    }
}

// ---------------------------------------------------------------------------
// launch
// ---------------------------------------------------------------------------
extern "C" void kernel_launch(void* const* d_in, const int* in_sizes, int n_in,
                              void* d_out, int out_size) {
    const float* x     = (const float*)d_in[0];   // (32768, 1, 1024)
    const float* theta = (const float*)d_in[1];   // (256, 4)
    const float* W     = (const float*)d_in[2];   // (1024, 1024)
    const float* b     = (const float*)d_in[3];   // (1024,)
    float* out = (float*)d_out;

    prep_kernel<<<PRE_BLOCKS + PERM_BLOCKS, 256>>>(x, theta, W);

    const int smem_bytes = STAGES * STAGE_BYTES + 1024;   // 97.25 KB
    cudaFuncSetAttribute(qmha_gemm_kernel,
                         cudaFuncAttributeMaxDynamicSharedMemorySize, smem_bytes);

    dim3 grid((M_TOT / BM) * (N_TOT / BN));       // 2048
    qmha_gemm_kernel<<<grid, 128, smem_bytes>>>(b, out);
}

// round 17
// speedup vs baseline: 1.0577x; 1.0577x over previous
#include <cuda_runtime.h>
#include <cuda_fp16.h>
#include <cstdint>

#define M_TOT 32768
#define N_TOT 1024
#define K_TOT 1024
#define BM 128
#define BN 128
#define BK 64
#define STAGES 3
#define TILE_BYTES 16384               // one 128x64 fp16 tile, swizzled
#define STAGE_BYTES (2 * TILE_BYTES)   // A tile + B tile
#define NKT (K_TOT / BK)               // 16
#define SLAB_BYTES ((size_t)NKT * TILE_BYTES)
#define PRE_BLOCKS 16384
#define PERM_BLOCKS 512

// scratch, both stored TILED + SWIZZLED:
//   g_Ah:  [bm_blk=256][kt=16][128x64 tile, 16KB, xor-swizzled]   (64 MB)
//   g_Wph: [bn_blk=8  ][kt=16][128x64 tile, 16KB, xor-swizzled]   ( 2 MB)
__device__ __half g_Ah[(size_t)M_TOT * K_TOT];
__device__ __half g_Wph[N_TOT * K_TOT];

__device__ __forceinline__ uint32_t tile_off(int row, int cc) {
    return (uint32_t)row * 128u + (uint32_t)((cc ^ (row & 7)) << 4);
}

// ---------------------------------------------------------------------------
// Kernel 0 (fused prep):
//  blocks [0, PRE_BLOCKS): A = fp16(__cosf(x+theta)), tiled layout, with
//    A slabs written in REVERSE order (slab 255 first, slab 0 last) so the
//    GEMM's first waves (slabs 0..36, 9.5 MB) are L2-resident when it starts.
//    Row order within slabs is preserved -> coalescing byte-identical to R9.
//  blocks [PRE_BLOCKS, +PERM_BLOCKS): Wph[n, h*4+q] = fp16(W[n, q*256+h])
//    (written last -> all 2 MB of W hot in L2 for the GEMM)
// ---------------------------------------------------------------------------
__global__ void prep_kernel(const float* __restrict__ X,
                            const float* __restrict__ theta,
                            const float* __restrict__ W) {
    if (blockIdx.x < PRE_BLOCKS) {
        const size_t idx = (size_t)blockIdx.x * blockDim.x + threadIdx.x; // half8 id
        const float4* X4  = (const float4*)X;
        const float4* Th4 = (const float4*)theta;
        const int k8 = (int)(idx & (K_TOT / 8 - 1));       // 0..127
        const int m_orig = (int)(idx >> 7);
        // reverse slab order, keep row order within slab
        const int m = ((255 - (m_orig >> 7)) << 7) | (m_orig & 127);
        const float4 t0 = __ldg(Th4 + 2 * k8);
        const float4 t1 = __ldg(Th4 + 2 * k8 + 1);
        const float4 v0 = __ldg(X4 + (size_t)m * 256 + 2 * k8);
        const float4 v1 = __ldg(X4 + (size_t)m * 256 + 2 * k8 + 1);
        __half h[8];
        h[0] = __float2half_rn(__cosf(v0.x + t0.x));
        h[1] = __float2half_rn(__cosf(v0.y + t0.y));
        h[2] = __float2half_rn(__cosf(v0.z + t0.z));
        h[3] = __float2half_rn(__cosf(v0.w + t0.w));
        h[4] = __float2half_rn(__cosf(v1.x + t1.x));
        h[5] = __float2half_rn(__cosf(v1.y + t1.y));
        h[6] = __float2half_rn(__cosf(v1.z + t1.z));
        h[7] = __float2half_rn(__cosf(v1.w + t1.w));
        const int bm_blk = m >> 7;
        const int rowloc = m & 127;
        const int kt = k8 >> 3;
        const int cc = k8 & 7;
        const size_t dst = (size_t)bm_blk * SLAB_BYTES
                         + (size_t)kt * TILE_BYTES + tile_off(rowloc, cc);
        *(uint4*)((char*)g_Ah + dst) = *(const uint4*)h;
    } else {
        const int base = ((int)blockIdx.x - PRE_BLOCKS) * (256 * 8)
                       + (int)threadIdx.x * 8;
#pragma unroll
        for (int e = 0; e < 8; e++) {
            const int idx = base + e;          // 0 .. 1M-1
            const int n = idx >> 10;
            const int j = idx & 1023;
            const int q = j >> 8;
            const int hh = j & 255;
            const int k = (hh << 2) | q;
            const int bn_blk = n >> 7;
            const int rowloc = n & 127;
            const int kt = k >> 6;
            const int cc = (k >> 3) & 7;
            const size_t dst = (size_t)bn_blk * SLAB_BYTES
                             + (size_t)kt * TILE_BYTES + tile_off(rowloc, cc)
                             + (size_t)((k & 7) * 2);
            *(__half*)((char*)g_Wph + dst) = __float2half_rn(__ldg(W + idx));
        }
    }
}

// ---------------------------------------------------------------------------
// helpers
// ---------------------------------------------------------------------------
__device__ __forceinline__ uint32_t smem_u32(const void* p) {
    uint32_t a;
    asm("{ .reg .u64 t; cvta.to.shared.u64 t, %1; cvt.u32.u64 %0, t; }"
        : "=r"(a) : "l"(p));
    return a;
}

#define MBAR_INIT(addr, cnt) \
    asm volatile("mbarrier.init.shared.b64 [%0], %1;" :: "r"(addr), "r"(cnt) : "memory")

#define MBAR_EXPECT_TX(addr, bytes) \
    asm volatile("mbarrier.arrive.expect_tx.shared.b64 _, [%0], %1;" \
                 :: "r"(addr), "r"(bytes) : "memory")

#define MBAR_ARRIVE(addr) \
    asm volatile("mbarrier.arrive.release.cta.shared.b64 _, [%0];" \
                 :: "r"(addr) : "memory")

#define MBAR_WAIT(addr, parity) do {                                              \
    asm volatile("{\n\t.reg .pred P1;\n\t"                                        \
        "LAB_W_%=:\n\t"                                                           \
        "mbarrier.try_wait.parity.acquire.cta.shared::cta.b64 P1, [%0], %1, 0x989680;\n\t" \
        "@P1 bra.uni LAB_D_%=;\n\t"                                               \
        "bra.uni LAB_W_%=;\n\t"                                                   \
        "LAB_D_%=:\n\t}"                                                          \
        :: "r"(addr), "r"(parity) : "memory");                                    \
} while (0)

#define FENCE_ASYNC() \
    asm volatile("fence.proxy.async.shared::cta;" ::: "memory")

#define BULK_CP(dst, src, bytes, mbar) \
    asm volatile("cp.async.bulk.shared::cluster.global.mbarrier::complete_tx::bytes " \
                 "[%0], [%1], %2, [%3];" \
                 :: "r"(dst), "l"(src), "r"(bytes), "r"(mbar) : "memory")

__device__ __forceinline__ void ldsm_x4(uint32_t* r, uint32_t addr) {
    asm volatile("ldmatrix.sync.aligned.m8n8.x4.shared.b16 {%0,%1,%2,%3}, [%4];"
                 : "=r"(r[0]), "=r"(r[1]), "=r"(r[2]), "=r"(r[3]) : "r"(addr));
}

__device__ __forceinline__ void mma_f16(float* c, const uint32_t* a,
                                        const uint32_t* b) {
    asm volatile(
        "mma.sync.aligned.m16n8k16.row.col.f32.f16.f16.f32 "
        "{%0,%1,%2,%3}, {%4,%5,%6,%7}, {%8,%9}, {%0,%1,%2,%3};\n"
        : "+f"(c[0]), "+f"(c[1]), "+f"(c[2]), "+f"(c[3])
        : "r"(a[0]), "r"(a[1]), "r"(a[2]), "r"(a[3]), "r"(b[0]), "r"(b[1]));
}

// ---------------------------------------------------------------------------
// Kernel 1: out = Ah @ Wph^T + bias   (bit-exact R9 GEMM)
//   block 128x128, BK=64, 4 warps (2M x 2N), warp tile 64x64, 2 CTA/SM,
//   3-stage cp.async.bulk + full/empty mbarriers + proxy fence
// ---------------------------------------------------------------------------
__global__ void __launch_bounds__(128, 2)
qmha_gemm_kernel(const float* __restrict__ bias, float* __restrict__ out) {
    extern __shared__ char dsm[];
    __shared__ __align__(8) uint64_t bar_s[2 * STAGES];   // full[3], empty[3]

    const uint32_t base = (smem_u32(dsm) + 1023u) & ~1023u;
    const uint32_t full_bar  = smem_u32(bar_s);
    const uint32_t empty_bar = full_bar + 8 * STAGES;

    const int tid  = threadIdx.x;
    const int warp = tid >> 5;
    const int lane = tid & 31;
    const int g    = lane >> 2;
    const int t    = lane & 3;
    const int wm   = (warp & 1) * 64;     // 2 warps along M
    const int wn   = (warp >> 1) * 64;    // 2 warps along N

    // block swizzle: N fastest -> co-resident blocks share A slab in L2
    const int bn_blk = blockIdx.x & 7;
    const int bm_blk = blockIdx.x >> 3;
    const int bn = bn_blk * BN;
    const int bm = bm_blk * BM;

    const char* aChunk = (const char*)g_Ah + (size_t)bm_blk * SLAB_BYTES;
    const char* bChunk = (const char*)g_Wph + (size_t)bn_blk * SLAB_BYTES;

    if (tid == 0) {
#pragma unroll
        for (int s = 0; s < STAGES; s++) {
            MBAR_INIT(full_bar + 8 * s, 1);
            MBAR_INIT(empty_bar + 8 * s, 4);    // one arrive per warp
        }
    }
    __syncthreads();

    auto ISSUE = [&](int s, int kt) {
        const uint32_t fb = full_bar + 8 * s;
        MBAR_EXPECT_TX(fb, STAGE_BYTES);
        BULK_CP(base + s * STAGE_BYTES, aChunk + (size_t)kt * TILE_BYTES,
                TILE_BYTES, fb);
        BULK_CP(base + s * STAGE_BYTES + TILE_BYTES,
                bChunk + (size_t)kt * TILE_BYTES, TILE_BYTES, fb);
    };

    uint32_t ep = 4;                    // empty-parity bits {s0:0, s1:0, s2:1}
    if (tid == 0) { ISSUE(0, 0); ISSUE(1, 1); }

    // ldmatrix per-lane address components
    const int rA  = lane & 15;
    const int aHi = lane >> 4;
    const uint32_t aRowB = (uint32_t)(wm + rA) * 128;
    const uint32_t aSw   = (uint32_t)(rA & 7);
    const int nLoc = (lane & 7) | ((lane >> 4) << 3);
    const int bHi  = (lane >> 3) & 1;
    const uint32_t bRowB = (uint32_t)(wn + nLoc) * 128;
    const uint32_t bSw   = (uint32_t)(nLoc & 7);

    float acc[4][8][4];
#pragma unroll
    for (int m = 0; m < 4; m++)
#pragma unroll
        for (int n = 0; n < 8; n++)
#pragma unroll
            for (int v = 0; v < 4; v++) acc[m][n][v] = 0.f;

    int stage = 0, parity = 0;
    for (int kt = 0; kt < NKT; kt++) {
        // issuer: refill stage kt+2 once all 4 warps released it
        if (tid == 0 && kt + 2 < NKT) {
            const int s2 = stage + 2 >= STAGES ? stage + 2 - STAGES : stage + 2;
            MBAR_WAIT(empty_bar + 8 * s2, (ep >> s2) & 1);
            ep ^= 1u << s2;
            FENCE_ASYNC();              // order generic reads before TMA rewrite
            ISSUE(s2, kt + 2);
        }

        MBAR_WAIT(full_bar + 8 * stage, parity);

        const uint32_t aS = base + stage * STAGE_BYTES + aRowB;
        const uint32_t bS = base + stage * STAGE_BYTES + TILE_BYTES + bRowB;
#pragma unroll
        for (int ks = 0; ks < 4; ks++) {               // 4 x k16 per BK=64
            const uint32_t ca = (uint32_t)((((2 * ks) | aHi) ^ aSw) << 4);
            const uint32_t cb = (uint32_t)((((2 * ks) | bHi) ^ bSw) << 4);
            uint32_t af[4][4], bf[4][4];
#pragma unroll
            for (int mt = 0; mt < 4; mt++)
                ldsm_x4(af[mt], aS + mt * 2048 + ca);
#pragma unroll
            for (int p = 0; p < 4; p++)
                ldsm_x4(bf[p], bS + p * 2048 + cb);
#pragma unroll
            for (int mt = 0; mt < 4; mt++)
#pragma unroll
                for (int nt = 0; nt < 8; nt++)
                    mma_f16(acc[mt][nt], af[mt], &bf[nt >> 1][(nt & 1) * 2]);
        }

        if (lane == 0) MBAR_ARRIVE(empty_bar + 8 * stage);

        stage = stage + 1 >= STAGES ? 0 : stage + 1;
        if (stage == 0) parity ^= 1;
    }

    // epilogue: + bias, fp32 out (64x64 per warp)
#pragma unroll
    for (int mt = 0; mt < 4; mt++) {
        const int m = bm + wm + mt * 16 + g;
#pragma unroll
        for (int nt = 0; nt < 8; nt++) {
            const int n = bn + wn + nt * 8 + 2 * t;
            const float b0 = __ldg(bias + n);
            const float b1 = __ldg(bias + n + 1);
            *(float2*)(out + (size_t)m * N_TOT + n) =
                make_float2(acc[mt][nt][0] + b0, acc[mt][nt][1] + b1);
            *(float2*)(out + (size_t)(m + 8) * N_TOT + n) =
                make_float2(acc[mt][nt][2] + b0, acc[mt][nt][3] + b1);
        }
    }
}

// ---------------------------------------------------------------------------
// launch
// ---------------------------------------------------------------------------
extern "C" void kernel_launch(void* const* d_in, const int* in_sizes, int n_in,
                              void* d_out, int out_size) {
    const float* x     = (const float*)d_in[0];   // (32768, 1, 1024)
    const float* theta = (const float*)d_in[1];   // (256, 4)
    const float* W     = (const float*)d_in[2];   // (1024, 1024)
    const float* b     = (const float*)d_in[3];   // (1024,)
    float* out = (float*)d_out;

    prep_kernel<<<PRE_BLOCKS + PERM_BLOCKS, 256>>>(x, theta, W);

    const int smem_bytes = STAGES * STAGE_BYTES + 1024;   // 97.25 KB
    cudaFuncSetAttribute(qmha_gemm_kernel,
                         cudaFuncAttributeMaxDynamicSharedMemorySize, smem_bytes);

    dim3 grid((M_TOT / BM) * (N_TOT / BN));       // 2048
    qmha_gemm_kernel<<<grid, 128, smem_bytes>>>(b, out);
}